// round 15
// baseline (speedup 1.0000x reference)
#include <cuda_runtime.h>
#include <cuda_fp16.h>
#include <cstdint>

#define T 256
#define H 128
#define V 60
#define M 4            // batch rows per CTA
#define NT 256
#define NCTA 256       // 2 CTAs per SM
#define PSW 132

// ---- shared layout (float-word offsets) ------------------------------------
// main fp16 tile (per buffer 512 words): pair idx = kt*32 + kq*8 + (n ^ kq)
//   pair bytes [0:4) = f16x2 of k {kt*16+2kq, +1}, [4:8) = k {+8}; col n = 2m + s
//   (s=0: h_hi, s=1: h_lo residual)
// fp8 tile (per buffer 256 words): pair idx = q*32 + cp*8 + (n ^ cp)
//   bytes [0:4) = e4m3 k {q*32+4cp..+3}, [4:8) = k {+16}; col n = 2m (odd cols 0)
#define MAIN_OFF(s) ((s) * 512)
#define F8_OFF(s)   (1024 + (s) * 256)
#define PS_OFF      1536
#define LS_OFF      (PS_OFF + V * PSW)
#define TOK_OFF     (LS_OFF + M * H)
#define SMWORDS     (TOK_OFF + M * T)

__device__ __align__(16) float g_proj[V * H];

__device__ __forceinline__ float fast_tanh(float x) {
    float e = __expf(2.0f * x);
    return 1.0f - __fdividef(2.0f, e + 1.0f);
}
__device__ __forceinline__ void mma_f16(float* c, const uint32_t* a,
                                        uint32_t b0, uint32_t b1) {
    asm volatile(
        "mma.sync.aligned.m16n8k16.row.col.f32.f16.f16.f32 "
        "{%0,%1,%2,%3}, {%4,%5,%6,%7}, {%8,%9}, {%0,%1,%2,%3};"
        : "+f"(c[0]), "+f"(c[1]), "+f"(c[2]), "+f"(c[3])
        : "r"(a[0]), "r"(a[1]), "r"(a[2]), "r"(a[3]), "r"(b0), "r"(b1));
}
__device__ __forceinline__ void mma_fp8(float* c, const uint32_t* a,
                                        uint32_t b0, uint32_t b1) {
    asm volatile(
        "mma.sync.aligned.m16n8k32.row.col.f32.e4m3.e4m3.f32 "
        "{%0,%1,%2,%3}, {%4,%5,%6,%7}, {%8,%9}, {%0,%1,%2,%3};"
        : "+f"(c[0]), "+f"(c[1]), "+f"(c[2]), "+f"(c[3])
        : "r"(a[0]), "r"(a[1]), "r"(a[2]), "r"(a[3]), "r"(b0), "r"(b1));
}
__device__ __forceinline__ uint16_t e4m3x2(float x1, float x0) {  // low byte = x0
    uint16_t r;
    asm("cvt.rn.satfinite.e4m3x2.f32 %0, %1, %2;" : "=h"(r) : "f"(x1), "f"(x0));
    return r;
}
__device__ __forceinline__ uint32_t pack_e4m3_4(float x0, float x1, float x2, float x3) {
    uint16_t lo = e4m3x2(x1, x0);
    uint16_t hi = e4m3x2(x3, x2);
    return ((uint32_t)hi << 16) | lo;
}
__device__ __forceinline__ uint32_t pack_f16(float a, float b) {  // low = a
    __half2 h = __floats2half2_rn(a, b);
    return *(uint32_t*)&h;
}

// ---------------------------------------------------------------------------
// Stage 1: proj[v][j] = emb[v] . W_ih[j]
// ---------------------------------------------------------------------------
__global__ void proj_kernel(const float* __restrict__ emb,
                            const float* __restrict__ W_ih) {
    __shared__ float e[H];
    const int v = blockIdx.x;
    const int j = threadIdx.x;
    e[j] = emb[v * H + j];
    __syncthreads();
    const float* w = W_ih + j * H;
    float s = 0.f;
#pragma unroll 16
    for (int k = 0; k < H; ++k) s += e[k] * w[k];
    g_proj[v * H + j] = s;
}

// ---------------------------------------------------------------------------
// Stage 2: 2 CTAs/SM, M=4 rows each. Main z = f16(W)*(h_hi cols + h_lo cols)
// via 8 fp16 MMAs; correction Wlo*h via 4 fp8 MMAs (even cols only).
// Thread (w, g, c): j1 = 16w+g, j2 = j1+8, m = c. One barrier per step.
// ---------------------------------------------------------------------------
__global__ __launch_bounds__(NT, 2)
void rnn_kernel(const int* __restrict__ x,
                const int* __restrict__ lengths,
                const float* __restrict__ W_hh,
                const float* __restrict__ W_fc,
                const float* __restrict__ b_fc,
                float* __restrict__ out) {
    extern __shared__ float sm[];
    float* Ps  = sm + PS_OFF;
    float* Ls  = sm + LS_OFF;
    int*   Tok = (int*)(sm + TOK_OFF);

    const int tid = threadIdx.x;
    const int w = tid >> 5, l = tid & 31;
    const int g = l >> 2, c = l & 3;
    const int b0 = blockIdx.x * M;

    for (int idx = tid; idx < V * H; idx += NT) {
        int v = idx >> 7, j = idx & 127;
        Ps[v * PSW + j] = g_proj[idx];
    }
    for (int idx = tid; idx < M * T; idx += NT)
        Tok[idx] = x[b0 * T + idx];
    for (int idx = tid; idx < 1536; idx += NT)   // zero both tile buffers
        sm[idx] = 0.f;

    const int j1 = w * 16 + g;
    const int j2 = j1 + 8;

    // --- fp16 main A fragments: A = f16(W) ---
    uint32_t Af[8][4];
#pragma unroll
    for (int kt = 0; kt < 8; ++kt) {
        const float* r1 = W_hh + j1 * H + kt * 16;
        const float* r2 = W_hh + j2 * H + kt * 16;
        Af[kt][0] = pack_f16(r1[2 * c], r1[2 * c + 1]);
        Af[kt][1] = pack_f16(r2[2 * c], r2[2 * c + 1]);
        Af[kt][2] = pack_f16(r1[8 + 2 * c], r1[8 + 2 * c + 1]);
        Af[kt][3] = pack_f16(r2[8 + 2 * c], r2[8 + 2 * c + 1]);
    }
    // --- fp8 correction A fragments: e4m3(Wlo * 2048) ---
    uint32_t AL8[4][4];
#pragma unroll
    for (int q = 0; q < 4; ++q) {
        const int rows[2] = { j1, j2 };
#pragma unroll
        for (int half = 0; half < 2; ++half) {
#pragma unroll
            for (int rr = 0; rr < 2; ++rr) {
                const float* p = W_hh + rows[rr] * H + q * 32 + half * 16 + 4 * c;
                float l0 = (p[0] - __half2float(__float2half_rn(p[0]))) * 2048.f;
                float l1 = (p[1] - __half2float(__float2half_rn(p[1]))) * 2048.f;
                float l2 = (p[2] - __half2float(__float2half_rn(p[2]))) * 2048.f;
                float l3 = (p[3] - __half2float(__float2half_rn(p[3]))) * 2048.f;
                AL8[q][half * 2 + rr] = pack_e4m3_4(l0, l1, l2, l3);
            }
        }
    }

    const int len = lengths[b0 + c];

    // --- store offsets (this thread produces h for (j1, m=c) and (j2, m=c)) ---
    // main: k = j1 -> kt = w, kq = g>>1, slot byte = 2*(g&1) (j1) / 4+2*(g&1) (j2)
    const int mbase = w * 256 + (g >> 1) * 64;
    const int ghiO = mbase + (((2 * c) ^ (g >> 1)) << 3);
    const int gloO = mbase + (((2 * c + 1) ^ (g >> 1)) << 3);
    const int pr = (g & 1) * 2;
    // fp8: q = w>>1; j1: cp = g>>2, j2: cp+2; byte tail = 4*(w&1) + (g&3); col 2c
    const int qf = w >> 1;
    const int cp1 = g >> 2, cp2 = cp1 + 2;
    const int f8b1 = (qf * 32 + cp1 * 8 + ((2 * c) ^ cp1)) * 8 + 4 * (w & 1) + (g & 3);
    const int f8b2 = (qf * 32 + cp2 * 8 + ((2 * c) ^ cp2)) * 8 + 4 * (w & 1) + (g & 3);
    // load offset (uint2 units within a kt/q block)
    const int ldo = c * 8 + (g ^ c);

    __syncthreads();

    auto store_h = [&](int s, float h1, float h2) {
        char* mn = (char*)(sm + MAIN_OFF(s));
        __half f1 = __float2half_rn(h1), f2 = __float2half_rn(h2);
        *(unsigned short*)(mn + ghiO + pr)     = __half_as_ushort(f1);
        *(unsigned short*)(mn + ghiO + 4 + pr) = __half_as_ushort(f2);
        __half r1 = __float2half_rn(h1 - __half2float(f1));
        __half r2 = __float2half_rn(h2 - __half2float(f2));
        *(unsigned short*)(mn + gloO + pr)     = __half_as_ushort(r1);
        *(unsigned short*)(mn + gloO + 4 + pr) = __half_as_ushort(r2);
        char* f8 = (char*)(sm + F8_OFF(s));
        uint16_t pk = e4m3x2(h2, h1);
        f8[f8b1] = (char)pk;
        f8[f8b2] = (char)(pk >> 8);
    };

    // --- peel step 0: h1 = tanh(proj[x_0]) ---
    {
        int tk = Tok[c * T];
        float h1 = fast_tanh(Ps[tk * PSW + j1]);
        float h2 = fast_tanh(Ps[tk * PSW + j2]);
        if (len == 1) { Ls[c * H + j1] = h1; Ls[c * H + j2] = h2; }
        store_h(0, h1, h2);
    }
    __syncthreads();

    const float s2 = 1.f / 2048.f;

    for (int i = 1; i < T; ++i) {
        const int rs = (i - 1) & 1, ws = i & 1;
        const uint2* Mc = (const uint2*)(sm + MAIN_OFF(rs));
        const uint2* Fc = (const uint2*)(sm + F8_OFF(rs));

        int tk = Tok[c * T + i];
        float p1 = Ps[tk * PSW + j1];
        float p2 = Ps[tk * PSW + j2];

        float aM0[4] = {0.f, 0.f, 0.f, 0.f}, aM1[4] = {0.f, 0.f, 0.f, 0.f};
        float a8a[4] = {0.f, 0.f, 0.f, 0.f}, a8b[4] = {0.f, 0.f, 0.f, 0.f};

#pragma unroll
        for (int kt = 0; kt < 8; ++kt) {
            uint2 bb = Mc[kt * 32 + ldo];
            mma_f16((kt & 1) ? aM1 : aM0, Af[kt], bb.x, bb.y);
        }
#pragma unroll
        for (int q = 0; q < 4; ++q) {
            uint2 ff = Fc[q * 32 + ldo];
            mma_fp8((q & 1) ? a8b : a8a, AL8[q], ff.x, ff.y);
        }

        // cols: 2c = (m=c, h_hi), 2c+1 = (m=c, h_lo); fp8 col 2c = Wlo*h
        float z1 = (aM0[0] + aM1[0]) + (aM0[1] + aM1[1]) + (a8a[0] + a8b[0]) * s2 + p1;
        float z2 = (aM0[2] + aM1[2]) + (aM0[3] + aM1[3]) + (a8a[2] + a8b[2]) * s2 + p2;
        float h1 = fast_tanh(z1);
        float h2 = fast_tanh(z2);

        if (i == len - 1) { Ls[c * H + j1] = h1; Ls[c * H + j2] = h2; }
        store_h(ws, h1, h2);
        __syncthreads();
    }

    // --- FC epilogue: out[b] = Ls[b] @ W_fc^T + b_fc (reuse Ps for W_fc) ---
    for (int idx = tid; idx < V * H; idx += NT) {
        int v = idx >> 7, j = idx & 127;
        Ps[v * PSW + j] = W_fc[idx];
    }
    __syncthreads();

    for (int p = tid; p < M * V; p += NT) {
        const int m = p / V, v = p % V;
        const float* lr = Ls + m * H;
        const float* wr = Ps + v * PSW;
        float s = b_fc[v];
#pragma unroll 8
        for (int k = 0; k < H; ++k) s += lr[k] * wr[k];
        out[(b0 + m) * V + v] = s;
    }
}

extern "C" void kernel_launch(void* const* d_in, const int* in_sizes, int n_in,
                              void* d_out, int out_size) {
    const int*   x       = (const int*)d_in[0];
    const int*   lengths = (const int*)d_in[1];
    const float* emb     = (const float*)d_in[2];
    const float* W_ih    = (const float*)d_in[3];
    const float* W_hh    = (const float*)d_in[4];
    const float* W_fc    = (const float*)d_in[5];
    const float* b_fc    = (const float*)d_in[6];
    float*       out     = (float*)d_out;

    proj_kernel<<<V, H>>>(emb, W_ih);

    size_t smem = (size_t)SMWORDS * sizeof(float);
    cudaFuncSetAttribute(rnn_kernel, cudaFuncAttributeMaxDynamicSharedMemorySize,
                         (int)smem);
    rnn_kernel<<<NCTA, NT, smem>>>(x, lengths, W_hh, W_fc, b_fc, out);
}

// round 16
// speedup vs baseline: 1.4497x; 1.4497x over previous
#include <cuda_runtime.h>
#include <cuda_fp16.h>
#include <cstdint>

#define T 256
#define H 128
#define V 60
#define M 4            // batch rows per CTA
#define NT 128         // 4 warps per CTA
#define NCTA 256       // 2 CTAs per SM (reg cap 256/thread at 256 thr/SM)
#define PSW 132

// ---- shared layout (float-word offsets) ------------------------------------
// B tile (per buffer 256 uint2 pairs): pair idx = kt*32 + kq*8 + (n ^ kq)
//   pair bytes [0:4) = f16x2 of k {kt*16+2kq, +1}, [4:8) = k {+8}; col n = 2m+s
//   (s=0: h_hi, s=1: h_lo residual); kt 0..7, kq 0..3, n 0..7
#define MAIN_OFF(s) ((s) * 512)
#define PS_OFF      1024
#define LS_OFF      (PS_OFF + V * PSW)
#define TOK_OFF     (LS_OFF + M * H)
#define SMWORDS     (TOK_OFF + M * T)

__device__ __align__(16) float g_proj[V * H];

__device__ __forceinline__ float fast_tanh(float x) {
    float e = __expf(2.0f * x);
    return 1.0f - __fdividef(2.0f, e + 1.0f);
}
__device__ __forceinline__ void mma_f16(float* c, const uint32_t* a,
                                        uint32_t b0, uint32_t b1) {
    asm volatile(
        "mma.sync.aligned.m16n8k16.row.col.f32.f16.f16.f32 "
        "{%0,%1,%2,%3}, {%4,%5,%6,%7}, {%8,%9}, {%0,%1,%2,%3};"
        : "+f"(c[0]), "+f"(c[1]), "+f"(c[2]), "+f"(c[3])
        : "r"(a[0]), "r"(a[1]), "r"(a[2]), "r"(a[3]), "r"(b0), "r"(b1));
}
__device__ __forceinline__ uint32_t pack_f16(float a, float b) {  // low = a
    __half2 h = __floats2half2_rn(a, b);
    return *(uint32_t*)&h;
}

// ---------------------------------------------------------------------------
// Stage 1: proj[v][j] = emb[v] . W_ih[j]
// ---------------------------------------------------------------------------
__global__ void proj_kernel(const float* __restrict__ emb,
                            const float* __restrict__ W_ih) {
    __shared__ float e[H];
    const int v = blockIdx.x;
    const int j = threadIdx.x;
    e[j] = emb[v * H + j];
    __syncthreads();
    const float* w = W_ih + j * H;
    float s = 0.f;
#pragma unroll 16
    for (int k = 0; k < H; ++k) s += e[k] * w[k];
    g_proj[v * H + j] = s;
}

// ---------------------------------------------------------------------------
// Stage 2: 2 small CTAs/SM (128 thr, M=4). Warp w owns j in [32w, 32w+32)
// as two m16n8k16 A-tiles. B cols = (m, split): col 2m = h_hi, 2m+1 = h_lo.
// 4 MMA/kt (2 tiles x {Whi, Wlo}) = 32 MMA/warp/step, 3-term fp16 split.
// ---------------------------------------------------------------------------
__global__ __launch_bounds__(NT, 2)
void rnn_kernel(const int* __restrict__ x,
                const int* __restrict__ lengths,
                const float* __restrict__ W_hh,
                const float* __restrict__ W_fc,
                const float* __restrict__ b_fc,
                float* __restrict__ out) {
    extern __shared__ float sm[];
    float* Ps  = sm + PS_OFF;
    float* Ls  = sm + LS_OFF;
    int*   Tok = (int*)(sm + TOK_OFF);

    const int tid = threadIdx.x;
    const int w = tid >> 5, l = tid & 31;
    const int g = l >> 2, c = l & 3;
    const int b0 = blockIdx.x * M;

    for (int idx = tid; idx < V * H; idx += NT) {
        int v = idx >> 7, j = idx & 127;
        Ps[v * PSW + j] = g_proj[idx];
    }
    for (int idx = tid; idx < M * T; idx += NT)
        Tok[idx] = x[b0 * T + idx];

    // this thread's 4 output rows (m = c for all): j = jA + {0, 8, 16, 24}
    const int jA = w * 32 + g;
    int jrow[4];
#pragma unroll
    for (int t = 0; t < 4; ++t) jrow[t] = jA + 8 * t;

    // --- A fragments: [tile][kt][reg], tile0 rows jA..(+8), tile1 rows +16/+24 ---
    uint32_t Ahi[2][8][4], Alo[2][8][4];
#pragma unroll
    for (int t = 0; t < 2; ++t) {
        const int j1 = jA + 16 * t, j2 = j1 + 8;
#pragma unroll
        for (int kt = 0; kt < 8; ++kt) {
            const float* r1 = W_hh + j1 * H + kt * 16;
            const float* r2 = W_hh + j2 * H + kt * 16;
            float a0 = r1[2 * c], a1 = r1[2 * c + 1];
            float b0f = r2[2 * c], b1f = r2[2 * c + 1];
            float c0 = r1[8 + 2 * c], c1 = r1[8 + 2 * c + 1];
            float d0 = r2[8 + 2 * c], d1 = r2[8 + 2 * c + 1];
            Ahi[t][kt][0] = pack_f16(a0, a1);
            Ahi[t][kt][1] = pack_f16(b0f, b1f);
            Ahi[t][kt][2] = pack_f16(c0, c1);
            Ahi[t][kt][3] = pack_f16(d0, d1);
            Alo[t][kt][0] = pack_f16(a0 - __half2float(__float2half_rn(a0)),
                                     a1 - __half2float(__float2half_rn(a1)));
            Alo[t][kt][1] = pack_f16(b0f - __half2float(__float2half_rn(b0f)),
                                     b1f - __half2float(__float2half_rn(b1f)));
            Alo[t][kt][2] = pack_f16(c0 - __half2float(__float2half_rn(c0)),
                                     c1 - __half2float(__float2half_rn(c1)));
            Alo[t][kt][3] = pack_f16(d0 - __half2float(__float2half_rn(d0)),
                                     d1 - __half2float(__float2half_rn(d1)));
        }
    }

    const int len = lengths[b0 + c];

    // --- store byte offsets for the 4 produced h values (k = jrow, cols 2c/2c+1) ---
    int sHI[4], sLO[4];
#pragma unroll
    for (int t = 0; t < 4; ++t) {
        const int j = jrow[t];
        const int kt = j >> 4, r = j & 15;
        const int kq = (r & 7) >> 1;
        const int tail = ((r >> 3) << 2) + ((r & 1) << 1);
        sHI[t] = ((kt * 32 + kq * 8 + ((2 * c) ^ kq)) << 3) + tail;
        sLO[t] = ((kt * 32 + kq * 8 + ((2 * c + 1) ^ kq)) << 3) + tail;
    }
    const int ldo = c * 8 + (g ^ c);   // load pair offset within kt block

    __syncthreads();

    auto store_h = [&](int s, const float* hv) {
        char* mn = (char*)(sm + MAIN_OFF(s));
#pragma unroll
        for (int t = 0; t < 4; ++t) {
            __half f = __float2half_rn(hv[t]);
            *(unsigned short*)(mn + sHI[t]) = __half_as_ushort(f);
            __half r = __float2half_rn(hv[t] - __half2float(f));
            *(unsigned short*)(mn + sLO[t]) = __half_as_ushort(r);
        }
    };

    // --- peel step 0: h1 = tanh(proj[x_0]) ---
    {
        int tk = Tok[c * T];
        float hv[4];
#pragma unroll
        for (int t = 0; t < 4; ++t) {
            hv[t] = fast_tanh(Ps[tk * PSW + jrow[t]]);
            if (len == 1) Ls[c * H + jrow[t]] = hv[t];
        }
        store_h(0, hv);
    }
    __syncthreads();

    for (int i = 1; i < T; ++i) {
        const int rs = (i - 1) & 1, ws = i & 1;
        const uint2* Mc = (const uint2*)(sm + MAIN_OFF(rs));

        int tk = Tok[c * T + i];
        float pj[4];
#pragma unroll
        for (int t = 0; t < 4; ++t) pj[t] = Ps[tk * PSW + jrow[t]];

        float aH[2][4], aL[2][4];
#pragma unroll
        for (int t = 0; t < 2; ++t)
#pragma unroll
            for (int e = 0; e < 4; ++e) { aH[t][e] = 0.f; aL[t][e] = 0.f; }

#pragma unroll
        for (int kt = 0; kt < 8; ++kt) {
            uint2 bb = Mc[kt * 32 + ldo];
            mma_f16(aH[0], Ahi[0][kt], bb.x, bb.y);
            mma_f16(aH[1], Ahi[1][kt], bb.x, bb.y);
            mma_f16(aL[0], Alo[0][kt], bb.x, bb.y);
            mma_f16(aL[1], Alo[1][kt], bb.x, bb.y);
        }

        // z = Whi*hhi (col 2c) + Whi*hlo (col 2c+1) + Wlo*hhi (col 2c)
        float hv[4];
        hv[0] = fast_tanh(aH[0][0] + aH[0][1] + aL[0][0] + pj[0]);
        hv[1] = fast_tanh(aH[0][2] + aH[0][3] + aL[0][2] + pj[1]);
        hv[2] = fast_tanh(aH[1][0] + aH[1][1] + aL[1][0] + pj[2]);
        hv[3] = fast_tanh(aH[1][2] + aH[1][3] + aL[1][2] + pj[3]);

        if (i == len - 1) {
#pragma unroll
            for (int t = 0; t < 4; ++t) Ls[c * H + jrow[t]] = hv[t];
        }
        store_h(ws, hv);
        __syncthreads();
    }

    // --- FC epilogue: out[b] = Ls[b] @ W_fc^T + b_fc (reuse Ps for W_fc) ---
    for (int idx = tid; idx < V * H; idx += NT) {
        int v = idx >> 7, j = idx & 127;
        Ps[v * PSW + j] = W_fc[idx];
    }
    __syncthreads();

    for (int p = tid; p < M * V; p += NT) {
        const int m = p / V, v = p % V;
        const float* lr = Ls + m * H;
        const float* wr = Ps + v * PSW;
        float s = b_fc[v];
#pragma unroll 8
        for (int k = 0; k < H; ++k) s += lr[k] * wr[k];
        out[(b0 + m) * V + v] = s;
    }
}

extern "C" void kernel_launch(void* const* d_in, const int* in_sizes, int n_in,
                              void* d_out, int out_size) {
    const int*   x       = (const int*)d_in[0];
    const int*   lengths = (const int*)d_in[1];
    const float* emb     = (const float*)d_in[2];
    const float* W_ih    = (const float*)d_in[3];
    const float* W_hh    = (const float*)d_in[4];
    const float* W_fc    = (const float*)d_in[5];
    const float* b_fc    = (const float*)d_in[6];
    float*       out     = (float*)d_out;

    proj_kernel<<<V, H>>>(emb, W_ih);

    size_t smem = (size_t)SMWORDS * sizeof(float);
    cudaFuncSetAttribute(rnn_kernel, cudaFuncAttributeMaxDynamicSharedMemorySize,
                         (int)smem);
    rnn_kernel<<<NCTA, NT, smem>>>(x, lengths, W_hh, W_fc, b_fc, out);
}